// round 16
// baseline (speedup 1.0000x reference)
#include <cuda_runtime.h>
#include <cuda_bf16.h>
#include <mma.h>
#include <math.h>

using namespace nvcuda;

#define DH 1024
#define DM 1024
#define BATCH 128
static constexpr float QK_SCALE = 0.03125f; // 1/sqrt(1024)

// -------- scratch (no allocations allowed) --------
__device__ __nv_bfloat16 g_xh[BATCH * DM];   // x split hi
__device__ __nv_bfloat16 g_xl[BATCH * DM];   // x split lo
__device__ __nv_bfloat16 g_hhh[BATCH * DH];  // h_head split hi
__device__ __nv_bfloat16 g_hhl[BATCH * DH];  // h_head split lo
__device__ float g_q[BATCH * DH];
__device__ float g_k[BATCH * DH];
__device__ float g_v[BATCH * DH];
__device__ float g_o[BATCH * DH];
__device__ float g_part[8][BATCH * DM];      // split-K partials for out_proj
__device__ float g_ip[BATCH];
__device__ float g_fp[BATCH];
__device__ float g_den[BATCH];

__device__ __forceinline__ float warp_sum(float v) {
    #pragma unroll
    for (int s = 16; s; s >>= 1) v += __shfl_xor_sync(0xffffffffu, v, s);
    return v;
}

// ============================================================
// Split-bf16 WMMA GEMM core. X pre-split (bf16 hi/lo in gmem);
// W fp32, split in-kernel. One-sync double-buffered pipeline.
//   Y[m,n] = sum_k X[m,k] * W[n,k]    (64x64 tile per block)
// ============================================================
#define KCH 32
#define BLD 40
#define ARR_B (64 * BLD * 2)         // 5120 B per array
#define BUF_B (4 * ARR_B)            // 20480 B per buffer set

__device__ __forceinline__ __nv_bfloat16* sm_arr(char* raw, int buf, int arr) {
    return (__nv_bfloat16*)(raw + buf * BUF_B + arr * ARR_B);
}

__device__ __forceinline__ void split_store_row(
    __nv_bfloat16* H, __nv_bfloat16* L, int r, int c, float4 v)
{
    __nv_bfloat16 hx = __float2bfloat16(v.x);
    __nv_bfloat16 hy = __float2bfloat16(v.y);
    __nv_bfloat16 hz = __float2bfloat16(v.z);
    __nv_bfloat16 hw = __float2bfloat16(v.w);
    __nv_bfloat16 lx = __float2bfloat16(v.x - __bfloat162float(hx));
    __nv_bfloat16 ly = __float2bfloat16(v.y - __bfloat162float(hy));
    __nv_bfloat16 lz = __float2bfloat16(v.z - __bfloat162float(hz));
    __nv_bfloat16 lw = __float2bfloat16(v.w - __bfloat162float(hw));
    *(__nv_bfloat162*)&H[r * BLD + c]     = __nv_bfloat162(hx, hy);
    *(__nv_bfloat162*)&H[r * BLD + c + 2] = __nv_bfloat162(hz, hw);
    *(__nv_bfloat162*)&L[r * BLD + c]     = __nv_bfloat162(lx, ly);
    *(__nv_bfloat162*)&L[r * BLD + c + 2] = __nv_bfloat162(lz, lw);
}

// Caller must __syncthreads() after return before reading YS.
__device__ __forceinline__ void gemm_wmma_ps(
    char* raw,
    const __nv_bfloat16* __restrict__ XHg, const __nv_bfloat16* __restrict__ XLg,
    const float* __restrict__ W,
    int m0, int n0, int kbeg, int nchunks)
{
    const int tid  = threadIdx.x;
    const int warp = tid >> 5;
    const int wm   = warp >> 1;
    const int wn   = warp & 1;

    wmma::fragment<wmma::accumulator, 16, 16, 16, float> acc[2];
    wmma::fill_fragment(acc[0], 0.f);
    wmma::fill_fragment(acc[1], 0.f);

    const int xr = tid >> 2;               // 0..63
    const int xc = (tid & 3) * 8;          // 0,8,16,24
    const __nv_bfloat16* __restrict__ xhg = XHg + (size_t)(m0 + xr) * DM + kbeg + xc;
    const __nv_bfloat16* __restrict__ xlg = XLg + (size_t)(m0 + xr) * DM + kbeg + xc;

    const int wr = tid >> 3;               // 0..31
    const int wc = (tid & 7) * 4;          // 0..28
    const float* __restrict__ wg  = W + (size_t)(n0 + wr) * DM + kbeg + wc;
    const float* __restrict__ wg2 = wg + 32 * DM;

    uint4  pxh = *(const uint4*)xhg;
    uint4  pxl = *(const uint4*)xlg;
    float4 pw0 = *(const float4*)wg;
    float4 pw1 = *(const float4*)wg2;

    *(uint4*)&sm_arr(raw,0,0)[xr * BLD + xc] = pxh;
    *(uint4*)&sm_arr(raw,0,1)[xr * BLD + xc] = pxl;
    split_store_row(sm_arr(raw,0,2), sm_arr(raw,0,3), wr,      wc, pw0);
    split_store_row(sm_arr(raw,0,2), sm_arr(raw,0,3), wr + 32, wc, pw1);
    __syncthreads();

    for (int kc = 0; kc < nchunks; kc++) {
        const int b = kc & 1;
        if (kc + 1 < nchunks) {
            pxh = *(const uint4*)(xhg + (kc + 1) * KCH);
            pxl = *(const uint4*)(xlg + (kc + 1) * KCH);
            pw0 = *(const float4*)(wg  + (kc + 1) * KCH);
            pw1 = *(const float4*)(wg2 + (kc + 1) * KCH);
        }

        const __nv_bfloat16* XH = sm_arr(raw, b, 0);
        const __nv_bfloat16* XL = sm_arr(raw, b, 1);
        const __nv_bfloat16* WH = sm_arr(raw, b, 2);
        const __nv_bfloat16* WL = sm_arr(raw, b, 3);

        #pragma unroll
        for (int ks = 0; ks < KCH; ks += 16) {
            wmma::fragment<wmma::matrix_a, 16, 16, 16, __nv_bfloat16, wmma::row_major> ah, al;
            wmma::load_matrix_sync(ah, &XH[(wm * 16) * BLD + ks], BLD);
            wmma::load_matrix_sync(al, &XL[(wm * 16) * BLD + ks], BLD);
            #pragma unroll
            for (int t = 0; t < 2; t++) {
                wmma::fragment<wmma::matrix_b, 16, 16, 16, __nv_bfloat16, wmma::col_major> bh, bl;
                wmma::load_matrix_sync(bh, &WH[(wn * 32 + t * 16) * BLD + ks], BLD);
                wmma::load_matrix_sync(bl, &WL[(wn * 32 + t * 16) * BLD + ks], BLD);
                wmma::mma_sync(acc[t], ah, bh, acc[t]);
                wmma::mma_sync(acc[t], ah, bl, acc[t]);
                wmma::mma_sync(acc[t], al, bh, acc[t]);
            }
        }

        if (kc + 1 < nchunks) {
            const int nb = b ^ 1;
            *(uint4*)&sm_arr(raw,nb,0)[xr * BLD + xc] = pxh;
            *(uint4*)&sm_arr(raw,nb,1)[xr * BLD + xc] = pxl;
            split_store_row(sm_arr(raw,nb,2), sm_arr(raw,nb,3), wr,      wc, pw0);
            split_store_row(sm_arr(raw,nb,2), sm_arr(raw,nb,3), wr + 32, wc, pw1);
            __syncthreads();
        }
    }

    __syncthreads();
    float* YS = (float*)raw;
    wmma::store_matrix_sync(&YS[(wm * 16) * 72 + wn * 32],      acc[0], 72, wmma::mem_row_major);
    wmma::store_matrix_sync(&YS[(wm * 16) * 72 + wn * 32 + 16], acc[1], 72, wmma::mem_row_major);
}

// ============================================================
// gate + x pre-split (one block per batch, 256 thr)
// ============================================================
__global__ void __launch_bounds__(256)
gate_presplit_kernel(const float* __restrict__ x,
                     const float* __restrict__ wi, const float* __restrict__ wib,
                     const float* __restrict__ wf, const float* __restrict__ wfb,
                     const float* __restrict__ mprev,
                     float* __restrict__ out_m)
{
    const int b = blockIdx.x;
    const int t = threadIdx.x;
    const float4 xv = ((const float4*)(x + (size_t)b * DM))[t];
    const float4 iv = ((const float4*)wi)[t];
    const float4 fv = ((const float4*)wf)[t];

    __nv_bfloat16 hx = __float2bfloat16(xv.x);
    __nv_bfloat16 hy = __float2bfloat16(xv.y);
    __nv_bfloat16 hz = __float2bfloat16(xv.z);
    __nv_bfloat16 hw = __float2bfloat16(xv.w);
    const size_t o = (size_t)b * DM + t * 4;
    *(__nv_bfloat162*)&g_xh[o]     = __nv_bfloat162(hx, hy);
    *(__nv_bfloat162*)&g_xh[o + 2] = __nv_bfloat162(hz, hw);
    *(__nv_bfloat162*)&g_xl[o]     = __nv_bfloat162(
        __float2bfloat16(xv.x - __bfloat162float(hx)),
        __float2bfloat16(xv.y - __bfloat162float(hy)));
    *(__nv_bfloat162*)&g_xl[o + 2] = __nv_bfloat162(
        __float2bfloat16(xv.z - __bfloat162float(hz)),
        __float2bfloat16(xv.w - __bfloat162float(hw)));

    float si = xv.x * iv.x + xv.y * iv.y + xv.z * iv.z + xv.w * iv.w;
    float sf = xv.x * fv.x + xv.y * fv.y + xv.z * fv.z + xv.w * fv.w;

    __shared__ float sbi[8], sbf[8];
    si = warp_sum(si); sf = warp_sum(sf);
    if ((t & 31) == 0) { sbi[t >> 5] = si; sbf[t >> 5] = sf; }
    __syncthreads();
    if (t == 0) {
        float zi = 0.f, zf = 0.f;
        #pragma unroll
        for (int w = 0; w < 8; w++) { zi += sbi[w]; zf += sbf[w]; }
        zi += *wib; zf += *wfb;
        const float mp = mprev[b];
        const float mt = fmaxf(zf + mp, zi);
        out_m[b] = mt;
        g_ip[b] = expf(zi - mt);
        g_fp[b] = expf(zf + mp - mt);
    }
}

// ============================================================
// Projections q/k/v/sigmoid(o): grid (16 n, 2 m, 4 mat), 256 thr
// ============================================================
__global__ void __launch_bounds__(256)
proj_kernel(const float* __restrict__ Wq, const float* __restrict__ Wk,
            const float* __restrict__ Wv, const float* __restrict__ Wo,
            const float* __restrict__ Wob)
{
    __shared__ __align__(16) char raw[2 * BUF_B];

    const int z = blockIdx.z;
    const float* __restrict__ W = (z == 0) ? Wq : (z == 1) ? Wk : (z == 2) ? Wv : Wo;
    float* __restrict__ Y = (z == 0) ? g_q : (z == 1) ? g_k : (z == 2) ? g_v : g_o;

    const int m0 = blockIdx.y * 64;
    const int n0 = blockIdx.x * 64;

    gemm_wmma_ps(raw, g_xh, g_xl, W, m0, n0, 0, DM / KCH);
    __syncthreads();

    const float* YS = (const float*)raw;
    const int tid = threadIdx.x;
    #pragma unroll
    for (int ii = 0; ii < 4; ii++) {
        const int idx = tid + ii * 256;
        const int r = idx >> 4;
        const int c = (idx & 15) * 4;
        float4 v = *(const float4*)&YS[r * 72 + c];
        const int n = n0 + c;
        if (z == 3) {
            v.x = 1.f / (1.f + expf(-(v.x + Wob[n + 0])));
            v.y = 1.f / (1.f + expf(-(v.y + Wob[n + 1])));
            v.z = 1.f / (1.f + expf(-(v.z + Wob[n + 2])));
            v.w = 1.f / (1.f + expf(-(v.w + Wob[n + 3])));
        } else if (z != 2) {
            v.x *= QK_SCALE; v.y *= QK_SCALE; v.z *= QK_SCALE; v.w *= QK_SCALE;
        }
        *(float4*)&Y[(size_t)(m0 + r) * DH + n] = v;
    }
}

// ============================================================
// n_t + denom (one block per batch, 256 thr)
// ============================================================
__global__ void __launch_bounds__(256)
ndenom_kernel(const float* __restrict__ nprev, float* __restrict__ out_n)
{
    const int b = blockIdx.x;
    const int t = threadIdx.x;
    const float ip = g_ip[b];
    const float f  = g_fp[b];
    const float4 np = ((const float4*)(nprev + (size_t)b * DH))[t];
    const float4 kv = ((const float4*)(g_k   + (size_t)b * DH))[t];
    const float4 qv = ((const float4*)(g_q   + (size_t)b * DH))[t];
    float4 n;
    n.x = f * np.x + ip * kv.x;
    n.y = f * np.y + ip * kv.y;
    n.z = f * np.z + ip * kv.z;
    n.w = f * np.w + ip * kv.w;
    ((float4*)(out_n + (size_t)b * DH))[t] = n;

    float s = n.x * qv.x + n.y * qv.y + n.z * qv.z + n.w * qv.w;
    __shared__ float sb[8];
    s = warp_sum(s);
    if ((t & 31) == 0) sb[t >> 5] = s;
    __syncthreads();
    if (t == 0) {
        float tot = 0.f;
        #pragma unroll
        for (int w = 0; w < 8; w++) tot += sb[w];
        g_den[b] = fmaxf(fabsf(tot), 1.f);
    }
}

// ============================================================
// Fused C update + Cq matvec + h_head (HBM-bound).
// R3-measured optimum geometry: 256 threads = 8 warps,
// grid (128 row-chunks, 128 batches) = 16384 blocks.
// Warp w owns row i: 8 batched LDG.128.cs (MLP=8), FMA,
// streaming stores, warp-reduced dot with q; bf16-split epilogue.
// ============================================================
__global__ void __launch_bounds__(256)
c_update_kernel(const float* __restrict__ Cprev, float* __restrict__ Cout)
{
    const int b = blockIdx.y;
    __shared__ float4 ks4[256];
    __shared__ float4 qs4[256];
    {
        const int t = threadIdx.x;
        ks4[t] = ((const float4*)(g_k + (size_t)b * DH))[t];
        qs4[t] = ((const float4*)(g_q + (size_t)b * DH))[t];
    }
    __syncthreads();

    const int warp = threadIdx.x >> 5;
    const int lane = threadIdx.x & 31;
    const int i = blockIdx.x * 8 + warp;

    const float f  = g_fp[b];
    const float iv = g_ip[b] * g_v[(size_t)b * DH + i];

    const float4* __restrict__ cp = (const float4*)(Cprev + ((size_t)b * DH + i) * DH);
    float4* __restrict__ co = (float4*)(Cout + ((size_t)b * DH + i) * DH);

    float4 c[8];
    #pragma unroll
    for (int u = 0; u < 8; u++) c[u] = __ldcs(&cp[u * 32 + lane]);

    float acc = 0.f;
    #pragma unroll
    for (int u = 0; u < 8; u++) {
        const int j4 = u * 32 + lane;
        const float4 k4 = ks4[j4];
        const float4 q4 = qs4[j4];
        float4 o;
        o.x = fmaf(f, c[u].x, iv * k4.x);
        o.y = fmaf(f, c[u].y, iv * k4.y);
        o.z = fmaf(f, c[u].z, iv * k4.z);
        o.w = fmaf(f, c[u].w, iv * k4.w);
        acc = fmaf(o.x, q4.x, acc);
        acc = fmaf(o.y, q4.y, acc);
        acc = fmaf(o.z, q4.z, acc);
        acc = fmaf(o.w, q4.w, acc);
        __stcs(&co[j4], o);
    }
    acc = warp_sum(acc);
    if (lane == 0) {
        const float hh = g_o[(size_t)b * DH + i] * acc / g_den[b];
        const __nv_bfloat16 hi = __float2bfloat16(hh);
        g_hhh[(size_t)b * DH + i] = hi;
        g_hhl[(size_t)b * DH + i] = __float2bfloat16(hh - __bfloat162float(hi));
    }
}

// ============================================================
// out_proj: split-K=8 wmma -> partials, grid (16 n, 2 m, 8 kz)
// ============================================================
__global__ void __launch_bounds__(256)
outproj_kernel(const float* __restrict__ P)
{
    __shared__ __align__(16) char raw[2 * BUF_B];

    const int z  = blockIdx.z;
    const int m0 = blockIdx.y * 64;
    const int n0 = blockIdx.x * 64;

    gemm_wmma_ps(raw, g_hhh, g_hhl, P, m0, n0, z * 128, 128 / KCH);
    __syncthreads();

    const float* YS = (const float*)raw;
    float* __restrict__ Yp = g_part[z];
    const int tid = threadIdx.x;
    #pragma unroll
    for (int ii = 0; ii < 4; ii++) {
        const int idx = tid + ii * 256;
        const int r = idx >> 4;
        const int c = (idx & 15) * 4;
        const float4 v = *(const float4*)&YS[r * 72 + c];
        *(float4*)&Yp[(size_t)(m0 + r) * DM + n0 + c] = v;
    }
}

__global__ void __launch_bounds__(256)
outproj_reduce_kernel(float* __restrict__ out_h)
{
    const int idx = blockIdx.x * 256 + threadIdx.x; // float4 index
    float4 r = {0.f, 0.f, 0.f, 0.f};
    #pragma unroll
    for (int p = 0; p < 8; p++) {
        const float4 a = ((const float4*)g_part[p])[idx];
        r.x += a.x; r.y += a.y; r.z += a.z; r.w += a.w;
    }
    ((float4*)out_h)[idx] = r;
}

// ============================================================
// launch (serial single-stream)
// ============================================================
extern "C" void kernel_launch(void* const* d_in, const int* in_sizes, int n_in,
                              void* d_out, int out_size)
{
    const float* x     = (const float*)d_in[0];
    const float* Cprev = (const float*)d_in[1];
    const float* nprev = (const float*)d_in[2];
    const float* mprev = (const float*)d_in[3];
    const float* Wq    = (const float*)d_in[4];
    const float* Wk    = (const float*)d_in[5];
    const float* Wv    = (const float*)d_in[6];
    const float* wi    = (const float*)d_in[7];
    const float* wib   = (const float*)d_in[8];
    const float* wf    = (const float*)d_in[9];
    const float* wfb   = (const float*)d_in[10];
    const float* Wo    = (const float*)d_in[11];
    const float* Wob   = (const float*)d_in[12];
    const float* P     = (const float*)d_in[13];

    float* out   = (float*)d_out;
    float* out_h = out;                                        // (B, 1024)
    float* out_c = out + (size_t)BATCH * DM;                   // (B, 1024, 1024)
    float* out_n = out_c + (size_t)BATCH * DH * DH;            // (B, 1024)
    float* out_m = out_n + (size_t)BATCH * DH;                 // (B,)

    gate_presplit_kernel<<<BATCH, 256>>>(x, wi, wib, wf, wfb, mprev, out_m);
    proj_kernel<<<dim3(16, 2, 4), 256>>>(Wq, Wk, Wv, Wo, Wob);
    ndenom_kernel<<<BATCH, 256>>>(nprev, out_n);
    c_update_kernel<<<dim3(128, BATCH), 256>>>(Cprev, out_c);
    outproj_kernel<<<dim3(16, 2, 8), 256>>>(P);
    outproj_reduce_kernel<<<128, 256>>>(out_h);
}